// round 3
// baseline (speedup 1.0000x reference)
#include <cuda_runtime.h>
#include <cuda_bf16.h>

// B=16384, NNEG=10, D=8, E=64, N_ENT=500000.
// score(x) = exp( exp(pair_w[0]) * 0.5 * ( ||sum_d e_d||^2 - sum_d ||e_d||^2 ) + c )
//
// TWO scores per warp: half-warp h (16 lanes) owns score 2*warp+h.
// Lane (l&15) owns float4 dims [4*(l&15) .. 4*(l&15)+3].
// Each LDG.128 loads one full 256B row for BOTH scores (lanes 0-15 row of
// score A, lanes 16-31 row of score B). All 8 row loads hoisted -> MLP=8
// of 512B warp-loads (4KB outstanding per warp).

#define D_DIM 8
#define E_DIM 64

__global__ __launch_bounds__(256) void APE_61555471286335_kernel(
    const int*   __restrict__ pos_x,     // [B, 8]
    const int*   __restrict__ neg_x,     // [B*NNEG, 8]
    const float* __restrict__ emb,       // [N_ENT, 64]
    const float* __restrict__ pair_w,    // [28]
    const float* __restrict__ cvec,      // [1]
    float*       __restrict__ out,       // [B + B*NNEG]
    int n_scores, int B)
{
    int warp  = (blockIdx.x * blockDim.x + threadIdx.x) >> 5;
    int lane  = threadIdx.x & 31;
    int half  = lane >> 4;        // which score within the warp
    int laneh = lane & 15;        // lane within half-warp

    int s = 2 * warp + half;      // this half-warp's score id
    bool active = (s < n_scores);
    int sc = active ? s : 0;      // clamp for safe loads

    const int* idxp = (sc < B) ? (pos_x + sc * D_DIM)
                               : (neg_x + (size_t)(sc - B) * D_DIM);

    // lanes 0..7 of each half-warp fetch the 8 indices (contiguous 32B)
    int myidx = (laneh < D_DIM) ? __ldg(idxp + laneh) : 0;

    // broadcast row indices within the half-warp, hoist all 8 gathers
    float4 v[D_DIM];
    #pragma unroll
    for (int d = 0; d < D_DIM; d++) {
        int row = __shfl_sync(0xffffffffu, myidx, (half << 4) + d);
        v[d] = __ldg(reinterpret_cast<const float4*>(
                         emb + (size_t)row * E_DIM) + laneh);
    }

    float sx = 0.f, sy = 0.f, sz = 0.f, sw = 0.f, sq = 0.f;
    #pragma unroll
    for (int d = 0; d < D_DIM; d++) {
        sx += v[d].x; sy += v[d].y; sz += v[d].z; sw += v[d].w;
        sq += v[d].x * v[d].x + v[d].y * v[d].y
            + v[d].z * v[d].z + v[d].w * v[d].w;
    }

    // per-lane contribution to ( ||S||^2 - sum ||e||^2 ), reduce over 16 lanes
    float val = sx * sx + sy * sy + sz * sz + sw * sw - sq;
    #pragma unroll
    for (int off = 8; off; off >>= 1)
        val += __shfl_xor_sync(0xffffffffu, val, off);

    if (laneh == 0 && active) {
        float w0 = expf(pair_w[0]);
        out[s] = expf(0.5f * val * w0 + cvec[0]);
    }
}

extern "C" void kernel_launch(void* const* d_in, const int* in_sizes, int n_in,
                              void* d_out, int out_size) {
    const int*   pos_x  = (const int*)  d_in[0];
    const int*   neg_x  = (const int*)  d_in[1];
    const float* emb    = (const float*)d_in[2];
    const float* pair_w = (const float*)d_in[3];
    const float* cvec   = (const float*)d_in[4];
    float*       out    = (float*)d_out;

    int B        = in_sizes[0] / D_DIM;              // 16384
    int n_neg    = in_sizes[1] / D_DIM;              // B*NNEG
    int n_scores = B + n_neg;                        // 180224

    int threads = 256;                               // 8 warps = 16 scores/block
    int scores_per_block = (threads / 32) * 2;
    int blocks = (n_scores + scores_per_block - 1) / scores_per_block;

    APE_61555471286335_kernel<<<blocks, threads>>>(
        pos_x, neg_x, emb, pair_w, cvec, out, n_scores, B);
}

// round 4
// speedup vs baseline: 1.0087x; 1.0087x over previous
#include <cuda_runtime.h>
#include <cuda_bf16.h>

// B=16384, NNEG=10, D=8, E=64, N_ENT=500000.
// score(x) = exp( exp(pair_w[0]) * 0.5 * ( ||sum_d e_d||^2 - sum_d ||e_d||^2 ) + c )
//
// TWO scores per warp: half-warp h (16 lanes) owns score 2*warp+h.
// Lane (l&15) owns float4 dims [4*(l&15) .. 4*(l&15)+3].
// Each LDG.128 loads one full 256B row for BOTH scores (lanes 0-15 row of
// score A, lanes 16-31 row of score B). All 8 row loads hoisted -> MLP=8
// of 512B warp-loads (4KB outstanding per warp).

#define D_DIM 8
#define E_DIM 64

__global__ __launch_bounds__(256) void APE_61555471286335_kernel(
    const int*   __restrict__ pos_x,     // [B, 8]
    const int*   __restrict__ neg_x,     // [B*NNEG, 8]
    const float* __restrict__ emb,       // [N_ENT, 64]
    const float* __restrict__ pair_w,    // [28]
    const float* __restrict__ cvec,      // [1]
    float*       __restrict__ out,       // [B + B*NNEG]
    int n_scores, int B)
{
    int warp  = (blockIdx.x * blockDim.x + threadIdx.x) >> 5;
    int lane  = threadIdx.x & 31;
    int half  = lane >> 4;        // which score within the warp
    int laneh = lane & 15;        // lane within half-warp

    int s = 2 * warp + half;      // this half-warp's score id
    bool active = (s < n_scores);
    int sc = active ? s : 0;      // clamp for safe loads

    const int* idxp = (sc < B) ? (pos_x + sc * D_DIM)
                               : (neg_x + (size_t)(sc - B) * D_DIM);

    // lanes 0..7 of each half-warp fetch the 8 indices (contiguous 32B)
    int myidx = (laneh < D_DIM) ? __ldg(idxp + laneh) : 0;

    // broadcast row indices within the half-warp, hoist all 8 gathers
    float4 v[D_DIM];
    #pragma unroll
    for (int d = 0; d < D_DIM; d++) {
        int row = __shfl_sync(0xffffffffu, myidx, (half << 4) + d);
        v[d] = __ldg(reinterpret_cast<const float4*>(
                         emb + (size_t)row * E_DIM) + laneh);
    }

    float sx = 0.f, sy = 0.f, sz = 0.f, sw = 0.f, sq = 0.f;
    #pragma unroll
    for (int d = 0; d < D_DIM; d++) {
        sx += v[d].x; sy += v[d].y; sz += v[d].z; sw += v[d].w;
        sq += v[d].x * v[d].x + v[d].y * v[d].y
            + v[d].z * v[d].z + v[d].w * v[d].w;
    }

    // per-lane contribution to ( ||S||^2 - sum ||e||^2 ), reduce over 16 lanes
    float val = sx * sx + sy * sy + sz * sz + sw * sw - sq;
    #pragma unroll
    for (int off = 8; off; off >>= 1)
        val += __shfl_xor_sync(0xffffffffu, val, off);

    if (laneh == 0 && active) {
        float w0 = expf(pair_w[0]);
        out[s] = expf(0.5f * val * w0 + cvec[0]);
    }
}

extern "C" void kernel_launch(void* const* d_in, const int* in_sizes, int n_in,
                              void* d_out, int out_size) {
    const int*   pos_x  = (const int*)  d_in[0];
    const int*   neg_x  = (const int*)  d_in[1];
    const float* emb    = (const float*)d_in[2];
    const float* pair_w = (const float*)d_in[3];
    const float* cvec   = (const float*)d_in[4];
    float*       out    = (float*)d_out;

    int B        = in_sizes[0] / D_DIM;              // 16384
    int n_neg    = in_sizes[1] / D_DIM;              // B*NNEG
    int n_scores = B + n_neg;                        // 180224

    int threads = 256;                               // 8 warps = 16 scores/block
    int scores_per_block = (threads / 32) * 2;
    int blocks = (n_scores + scores_per_block - 1) / scores_per_block;

    APE_61555471286335_kernel<<<blocks, threads>>>(
        pos_x, neg_x, emb, pair_w, cvec, out, n_scores, B);
}